// round 14
// baseline (speedup 1.0000x reference)
#include <cuda_runtime.h>
#include <cuda_fp16.h>

#define N_NODES  50000
#define N_EDGES  1600000
#define T_STEPS  50
#define DT_CONST 0.02f

#define NTHREADS 512
#define TN       (T_STEPS * N_NODES)
#define NTILE    8
#define TILE_N   6250                 // N_NODES / NTILE
#define NSEG     (NTILE * N_NODES)    // 400000 segments (tile, tgt)
#define MAXCTA   512
#define FULLMASK 0xFFFFFFFFu

// ---------------- device scratch (static, no allocation) ----------------
__device__ int      g_segdeg[NSEG];
__device__ int      g_segptr[NSEG + 1];
__device__ int      g_cursor[NSEG];
__device__ unsigned g_meta[N_EDGES];     // (srcLocal<<16) | fp16(w); 0 pad value is harmless
__device__ int      g_eseg[N_EDGES];     // segment id per sorted edge
__device__ float2   g_ab[N_NODES];       // {alpha, bias}
__device__ float4   g_V[N_NODES];        // membrane potential [n] x batch
__device__ uint2    g_Rh[N_NODES];       // fp16x4 rates (single buffer; phases are barrier-separated)
__device__ float4   g_part[NSEG];        // per-(tile,tgt) partials; consumed+rezeroed each step
__device__ int      g_blockSum[MAXCTA];
__device__ unsigned g_bar;

// ---------------- grid barrier (monotone counter, reset by init kernel) ----------------
__device__ __forceinline__ void grid_bar(unsigned k) {
    __syncthreads();
    if (threadIdx.x == 0) {
        __threadfence();
        atomicAdd(&g_bar, 1u);
        const unsigned target = k * gridDim.x;
        while (*(volatile unsigned*)&g_bar < target) { }
    }
    __syncthreads();
}

// ---------------- block-wide inclusive scan (Kogge-Stone in smem) ----------------
__device__ int block_scan_incl(int v) {
    __shared__ int ss[NTHREADS];
    const int tid = threadIdx.x;
    ss[tid] = v;
    __syncthreads();
#pragma unroll
    for (int off = 1; off < NTHREADS; off <<= 1) {
        int t = 0;
        if (tid >= off) t = ss[tid - off];
        __syncthreads();
        if (tid >= off) ss[tid] += t;
        __syncthreads();
    }
    return ss[tid];
}

// exclusive scan + block total (safe to call repeatedly)
__device__ int scan_excl_tot(int v, int& tot) {
    __shared__ int s_tot;
    int incl = block_scan_incl(v);
    if (threadIdx.x == NTHREADS - 1) s_tot = incl;
    __syncthreads();
    tot = s_tot;
    __syncthreads();
    return incl - v;
}

// ---------------- init kernel: reset per-launch mutable state ----------------
__global__ void init_kernel() {
    int i = blockIdx.x * blockDim.x + threadIdx.x;
    if (i == 0) g_bar = 0u;
    for (int s = i; s < NSEG; s += gridDim.x * blockDim.x) g_segdeg[s] = 0;
}

// ---------------- main persistent kernel ----------------
__global__ void __launch_bounds__(NTHREADS, 3) net_kernel(
    const float* __restrict__ x,       // [B, T, N]
    const float* __restrict__ bias,    // [N]
    const float* __restrict__ tconst,  // [N]
    const float* __restrict__ sign,    // [E]
    const float* __restrict__ cnt,     // [E]
    const float* __restrict__ strg,    // [E]
    const int*   __restrict__ src,     // [E]
    const int*   __restrict__ tgt,     // [E]
    float*       __restrict__ out,     // [B, T, N]
    int chunkN, int chunkS)
{
    extern __shared__ uint2 s_r[];     // this step's rates for my tile (50KB)

    const int tid  = threadIdx.x;
    const int bid  = blockIdx.x;
    const int ncta = gridDim.x;
    const int gtid = bid * NTHREADS + tid;
    const int nthr = ncta * NTHREADS;
    unsigned barK = 0;

    // ---- Pass A: histogram over segments (tile(src), tgt) ----
    for (int e = gtid; e < N_EDGES; e += nthr) {
        int seg = (src[e] / TILE_N) * N_NODES + tgt[e];
        atomicAdd(&g_segdeg[seg], 1);
    }
    grid_bar(++barK);

    // ---- Pass B1: per-CTA chunk scan (chunkS <= 1024, two rounds of 512) ----
    const int i0 = bid * chunkS + tid;
    const int i1 = i0 + NTHREADS;
    {
        int d0 = (tid < chunkS && i0 < NSEG) ? g_segdeg[i0] : 0;
        int d1 = (NTHREADS + tid < chunkS && i1 < NSEG) ? g_segdeg[i1] : 0;
        int tot0, tot1;
        int e0 = scan_excl_tot(d0, tot0);
        int e1 = scan_excl_tot(d1, tot1);
        if (tid < chunkS && i0 < NSEG) g_segptr[i0] = e0;
        if (NTHREADS + tid < chunkS && i1 < NSEG) g_segptr[i1] = e1 + tot0;
        if (tid == 0) g_blockSum[bid] = tot0 + tot1;
    }
    grid_bar(++barK);

    // ---- Pass B2: CTA0 exclusive-scans the block sums ----
    if (bid == 0) {
        int v = (tid < ncta) ? g_blockSum[tid] : 0;
        int t_;
        int ex = scan_excl_tot(v, t_);
        if (tid < ncta) g_blockSum[tid] = ex;
    }
    grid_bar(++barK);

    // ---- Pass B3: add block base -> final segptr & cursor ----
    {
        int boff = g_blockSum[bid];
        if (tid < chunkS && i0 < NSEG) {
            int v = g_segptr[i0] + boff;
            g_segptr[i0] = v;
            g_cursor[i0] = v;
        }
        if (NTHREADS + tid < chunkS && i1 < NSEG) {
            int v = g_segptr[i1] + boff;
            g_segptr[i1] = v;
            g_cursor[i1] = v;
        }
        if (gtid == 0) g_segptr[NSEG] = N_EDGES;
    }
    grid_bar(++barK);

    // ---- Pass C: scatter packed edge meta + seg id into segment slots ----
    for (int e = gtid; e < N_EDGES; e += nthr) {
        float w = sign[e] * fmaxf(cnt[e], 0.0f) * fmaxf(strg[e], 0.0f);
        int  s  = src[e];
        int  tile = s / TILE_N;
        int  sl   = s - tile * TILE_N;            // < 6250, fits 13 bits
        int  seg  = tile * N_NODES + tgt[e];
        int  p = atomicAdd(&g_cursor[seg], 1);
        unsigned hw = (unsigned)__half_as_ushort(__float2half_rn(w));
        g_meta[p] = ((unsigned)sl << 16) | hw;
        g_eseg[p] = seg;
    }

    // ---- Pass D: node state init + zero partials ----
    for (int n = gtid; n < N_NODES; n += nthr) {
        float b   = bias[n];
        float tau = fmaxf(tconst[n], DT_CONST);
        g_ab[n] = make_float2(DT_CONST / tau, b);
        g_V[n]  = make_float4(b, b, b, b);
        float r = fmaxf(b, 0.0f);
        __half2 h = __floats2half2_rn(r, r);
        uint2 hp;
        hp.x = *reinterpret_cast<unsigned*>(&h);
        hp.y = hp.x;
        g_Rh[n] = hp;
    }
    for (int s = gtid; s < NSEG; s += nthr)
        g_part[s] = make_float4(0.f, 0.f, 0.f, 0.f);
    grid_bar(++barK);   // meta + segptr + state all visible

    // ---- Hot-loop static assignment ----
    const int ctasPerTile = ncta / NTILE;          // ncta divisible by 8
    const int tile = bid / ctasPerTile;
    const int j    = bid - tile * ctasPerTile;
    const int tileNode0 = tile * TILE_N;
    const int tbeg = g_segptr[tile * N_NODES];
    const int tend = g_segptr[(tile + 1) * N_NODES];
    const int nch  = (tend - tbeg + 31) >> 5;      // 32-edge chunks in this tile

    const int wid  = tid >> 5;
    const int lane = tid & 31;
    const int gw   = j * (NTHREADS / 32) + wid;    // warp index within tile's CTA group
    const int tw   = ctasPerTile * (NTHREADS / 32);
    const int c0   = (int)((long long)nch * gw / tw);
    const int c1   = (int)((long long)nch * (gw + 1) / tw);

    const int  nodeE   = bid * chunkN + tid;
    const bool hasNode = (tid < chunkN) && (nodeE < N_NODES);

    for (int t = 0; t < T_STEPS; t++) {
        // ---- Phase 1: stage tile rates, then edge-parallel segmented-scan gather ----
        for (int i = tid; i < TILE_N; i += NTHREADS)
            s_r[i] = __ldcg(&g_Rh[tileNode0 + i]);
        __syncthreads();

        for (int ch = c0; ch < c1; ++ch) {         // uniform per-warp trip count
            const int e = tbeg + (ch << 5) + lane;
            const bool valid = (e < tend);
            int      seg = valid ? __ldg(&g_eseg[e]) : -1;   // coalesced
            unsigned m   = valid ? __ldg(&g_meta[e]) : 0u;   // coalesced; m=0 -> w=+0
            uint2 rh = s_r[m >> 16];                         // random LDS.64
            float w = __half2float(__ushort_as_half((unsigned short)(m & 0xFFFFu)));
            float2 f01 = __half22float2(*reinterpret_cast<__half2*>(&rh.x));
            float2 f23 = __half22float2(*reinterpret_cast<__half2*>(&rh.y));
            unsigned long long c01, c23;
            {
                float v0 = w * f01.x, v1 = w * f01.y, v2 = w * f23.x, v3 = w * f23.y;
                asm("mov.b64 %0, {%1, %2};" : "=l"(c01) : "f"(v0), "f"(v1));
                asm("mov.b64 %0, {%1, %2};" : "=l"(c23) : "f"(v2), "f"(v3));
            }
            // key-matched segmented inclusive scan (all lanes converged, full mask)
#pragma unroll
            for (int off = 1; off < 32; off <<= 1) {
                unsigned long long o01 = __shfl_up_sync(FULLMASK, c01, off);
                unsigned long long o23 = __shfl_up_sync(FULLMASK, c23, off);
                int os = __shfl_up_sync(FULLMASK, seg, off);
                unsigned long long s01, s23;
                asm("add.rn.f32x2 %0, %1, %2;" : "=l"(s01) : "l"(c01), "l"(o01));
                asm("add.rn.f32x2 %0, %1, %2;" : "=l"(s23) : "l"(c23), "l"(o23));
                bool p = (lane >= off) && (os == seg);
                c01 = p ? s01 : c01;
                c23 = p ? s23 : c23;
            }
            int ns = __shfl_down_sync(FULLMASK, seg, 1);
            bool tail = valid && (lane == 31 || ns != seg);
            if (tail) {
                float f0, f1, f2, f3;
                asm("mov.b64 {%0, %1}, %2;" : "=f"(f0), "=f"(f1) : "l"(c01));
                asm("mov.b64 {%0, %1}, %2;" : "=f"(f2), "=f"(f3) : "l"(c23));
                asm volatile("red.global.add.v4.f32 [%0], {%1, %2, %3, %4};"
                             :: "l"(&g_part[seg]), "f"(f0), "f"(f1), "f"(f2), "f"(f3)
                             : "memory");
            }
        }
        grid_bar(++barK);

        // ---- Phase 2: node-parallel Euler (all coalesced); consume + rezero parts ----
        if (hasNode) {
            float4 acc = make_float4(0.f, 0.f, 0.f, 0.f);
#pragma unroll
            for (int tl = 0; tl < NTILE; tl++) {
                float4* pp = &g_part[tl * N_NODES + nodeE];
                float4 p = __ldcg(pp);
                acc.x += p.x; acc.y += p.y; acc.z += p.z; acc.w += p.w;
                *pp = make_float4(0.f, 0.f, 0.f, 0.f);       // ready for next step
            }
            const float* xb = x + t * N_NODES + nodeE;
            float x0 = __ldcg(xb + 0 * TN);
            float x1 = __ldcg(xb + 1 * TN);
            float x2 = __ldcg(xb + 2 * TN);
            float x3 = __ldcg(xb + 3 * TN);

            float2 ab = g_ab[nodeE];
            float4 v  = g_V[nodeE];
            v.x = fmaf(ab.x, (ab.y - v.x) + (acc.x + x0), v.x);
            v.y = fmaf(ab.x, (ab.y - v.y) + (acc.y + x1), v.y);
            v.z = fmaf(ab.x, (ab.y - v.z) + (acc.z + x2), v.z);
            v.w = fmaf(ab.x, (ab.y - v.w) + (acc.w + x3), v.w);
            g_V[nodeE] = v;

            float r0 = fmaxf(v.x, 0.f), r1 = fmaxf(v.y, 0.f);
            float r2 = fmaxf(v.z, 0.f), r3 = fmaxf(v.w, 0.f);
            __half2 h01 = __floats2half2_rn(r0, r1);
            __half2 h23 = __floats2half2_rn(r2, r3);
            uint2 hp;
            hp.x = *reinterpret_cast<unsigned*>(&h01);
            hp.y = *reinterpret_cast<unsigned*>(&h23);
            g_Rh[nodeE] = hp;

            float* ob = out + t * N_NODES + nodeE;           // coalesced planes
            ob[0 * TN] = r0;
            ob[1 * TN] = r1;
            ob[2 * TN] = r2;
            ob[3 * TN] = r3;
        }
        if (t != T_STEPS - 1) grid_bar(++barK);
    }
}

extern "C" void kernel_launch(void* const* d_in, const int* in_sizes, int n_in,
                              void* d_out, int out_size) {
    const float* x      = (const float*)d_in[0];
    const float* bias   = (const float*)d_in[1];
    const float* tconst = (const float*)d_in[2];
    const float* sign   = (const float*)d_in[3];
    const float* cnt    = (const float*)d_in[4];
    const float* strg   = (const float*)d_in[5];
    const int*   src    = (const int*)d_in[6];
    const int*   tgt    = (const int*)d_in[7];
    float*       out    = (float*)d_out;

    // Attribute queries only (no alloc, no sync) -- capture-safe, deterministic.
    int nsm = 148;
    cudaDeviceGetAttribute(&nsm, cudaDevAttrMultiProcessorCount, 0);
    int ncta = (nsm * 3 / NTILE) * NTILE;    // multiple of NTILE, <= 3 per SM
    if (ncta > MAXCTA) ncta = MAXCTA;
    int chunkN = (N_NODES + ncta - 1) / ncta;
    int chunkS = (NSEG + ncta - 1) / ncta;   // <= 1024 for ncta >= 391

    static const int DYN = TILE_N * (int)sizeof(uint2);   // 50000 B
    cudaFuncSetAttribute(net_kernel, cudaFuncAttributeMaxDynamicSharedMemorySize, DYN);

    init_kernel<<<128, 512>>>();
    net_kernel<<<ncta, NTHREADS, DYN>>>(x, bias, tconst, sign, cnt, strg,
                                        src, tgt, out, chunkN, chunkS);
}

// round 15
// speedup vs baseline: 1.0223x; 1.0223x over previous
#include <cuda_runtime.h>
#include <cuda_fp16.h>

#define N_NODES  50000
#define N_EDGES  1600000
#define T_STEPS  50
#define DT_CONST 0.02f

#define NTHREADS 512
#define TN       (T_STEPS * N_NODES)
#define NTILE    8
#define TILE_N   6250                 // N_NODES / NTILE
#define NSEG     (NTILE * N_NODES)    // 400000 segments (tile, tgt)
#define MAXCTA   512
#define FULLMASK 0xFFFFFFFFu

// ---------------- device scratch (static, no allocation) ----------------
__device__ int      g_segdeg[NSEG];
__device__ int      g_segptr[NSEG + 1];
__device__ int      g_cursor[NSEG];
__device__ unsigned g_meta[N_EDGES];     // (srcLocal<<16) | fp16(w); 0 pad value is harmless
__device__ int      g_eseg[N_EDGES];     // segment id per sorted edge
__device__ float2   g_ab[N_NODES];       // {alpha, bias}
__device__ float4   g_V[N_NODES];        // membrane potential [n] x batch
__device__ uint2    g_Rh[N_NODES];       // fp16x4 rates (single buffer; phases are barrier-separated)
__device__ float4   g_part[NSEG];        // per-(tile,tgt) partials; consumed+rezeroed each step
__device__ int      g_blockSum[MAXCTA];
__device__ unsigned g_bar;

// ---------------- grid barrier (monotone counter, reset by init kernel) ----------------
__device__ __forceinline__ void grid_bar(unsigned k) {
    __syncthreads();
    if (threadIdx.x == 0) {
        __threadfence();
        atomicAdd(&g_bar, 1u);
        const unsigned target = k * gridDim.x;
        while (*(volatile unsigned*)&g_bar < target) { }
    }
    __syncthreads();
}

// ---------------- block-wide inclusive scan (Kogge-Stone in smem) ----------------
__device__ int block_scan_incl(int v) {
    __shared__ int ss[NTHREADS];
    const int tid = threadIdx.x;
    ss[tid] = v;
    __syncthreads();
#pragma unroll
    for (int off = 1; off < NTHREADS; off <<= 1) {
        int t = 0;
        if (tid >= off) t = ss[tid - off];
        __syncthreads();
        if (tid >= off) ss[tid] += t;
        __syncthreads();
    }
    return ss[tid];
}

// exclusive scan + block total (safe to call repeatedly)
__device__ int scan_excl_tot(int v, int& tot) {
    __shared__ int s_tot;
    int incl = block_scan_incl(v);
    if (threadIdx.x == NTHREADS - 1) s_tot = incl;
    __syncthreads();
    tot = s_tot;
    __syncthreads();
    return incl - v;
}

// ---------------- init kernel: reset per-launch mutable state ----------------
__global__ void init_kernel() {
    int i = blockIdx.x * blockDim.x + threadIdx.x;
    if (i == 0) g_bar = 0u;
    for (int s = i; s < NSEG; s += gridDim.x * blockDim.x) g_segdeg[s] = 0;
}

// ---------------- main persistent kernel ----------------
__global__ void __launch_bounds__(NTHREADS, 3) net_kernel(
    const float* __restrict__ x,       // [B, T, N]
    const float* __restrict__ bias,    // [N]
    const float* __restrict__ tconst,  // [N]
    const float* __restrict__ sign,    // [E]
    const float* __restrict__ cnt,     // [E]
    const float* __restrict__ strg,    // [E]
    const int*   __restrict__ src,     // [E]
    const int*   __restrict__ tgt,     // [E]
    float*       __restrict__ out,     // [B, T, N]
    int chunkN, int chunkS)
{
    extern __shared__ uint2 s_r[];     // this step's rates for my tile (50KB)

    const int tid  = threadIdx.x;
    const int bid  = blockIdx.x;
    const int ncta = gridDim.x;
    const int gtid = bid * NTHREADS + tid;
    const int nthr = ncta * NTHREADS;
    unsigned barK = 0;

    // ---- Pass A: histogram over segments (tile(src), tgt) ----
    for (int e = gtid; e < N_EDGES; e += nthr) {
        int seg = (src[e] / TILE_N) * N_NODES + tgt[e];
        atomicAdd(&g_segdeg[seg], 1);
    }
    grid_bar(++barK);

    // ---- Pass B1: per-CTA chunk scan (chunkS <= 1024, two rounds of 512) ----
    const int i0 = bid * chunkS + tid;
    const int i1 = i0 + NTHREADS;
    {
        int d0 = (tid < chunkS && i0 < NSEG) ? g_segdeg[i0] : 0;
        int d1 = (NTHREADS + tid < chunkS && i1 < NSEG) ? g_segdeg[i1] : 0;
        int tot0, tot1;
        int e0 = scan_excl_tot(d0, tot0);
        int e1 = scan_excl_tot(d1, tot1);
        if (tid < chunkS && i0 < NSEG) g_segptr[i0] = e0;
        if (NTHREADS + tid < chunkS && i1 < NSEG) g_segptr[i1] = e1 + tot0;
        if (tid == 0) g_blockSum[bid] = tot0 + tot1;
    }
    grid_bar(++barK);

    // ---- Pass B2: CTA0 exclusive-scans the block sums ----
    if (bid == 0) {
        int v = (tid < ncta) ? g_blockSum[tid] : 0;
        int t_;
        int ex = scan_excl_tot(v, t_);
        if (tid < ncta) g_blockSum[tid] = ex;
    }
    grid_bar(++barK);

    // ---- Pass B3: add block base -> final segptr & cursor ----
    {
        int boff = g_blockSum[bid];
        if (tid < chunkS && i0 < NSEG) {
            int v = g_segptr[i0] + boff;
            g_segptr[i0] = v;
            g_cursor[i0] = v;
        }
        if (NTHREADS + tid < chunkS && i1 < NSEG) {
            int v = g_segptr[i1] + boff;
            g_segptr[i1] = v;
            g_cursor[i1] = v;
        }
        if (gtid == 0) g_segptr[NSEG] = N_EDGES;
    }
    grid_bar(++barK);

    // ---- Pass C: scatter packed edge meta + seg id into segment slots ----
    for (int e = gtid; e < N_EDGES; e += nthr) {
        float w = sign[e] * fmaxf(cnt[e], 0.0f) * fmaxf(strg[e], 0.0f);
        int  s  = src[e];
        int  tile = s / TILE_N;
        int  sl   = s - tile * TILE_N;            // < 6250, fits 13 bits
        int  seg  = tile * N_NODES + tgt[e];
        int  p = atomicAdd(&g_cursor[seg], 1);
        unsigned hw = (unsigned)__half_as_ushort(__float2half_rn(w));
        g_meta[p] = ((unsigned)sl << 16) | hw;
        g_eseg[p] = seg;
    }

    // ---- Pass D: node state init + zero partials ----
    for (int n = gtid; n < N_NODES; n += nthr) {
        float b   = bias[n];
        float tau = fmaxf(tconst[n], DT_CONST);
        g_ab[n] = make_float2(DT_CONST / tau, b);
        g_V[n]  = make_float4(b, b, b, b);
        float r = fmaxf(b, 0.0f);
        __half2 h = __floats2half2_rn(r, r);
        uint2 hp;
        hp.x = *reinterpret_cast<unsigned*>(&h);
        hp.y = hp.x;
        g_Rh[n] = hp;
    }
    for (int s = gtid; s < NSEG; s += nthr)
        g_part[s] = make_float4(0.f, 0.f, 0.f, 0.f);
    grid_bar(++barK);   // meta + segptr + state all visible

    // ---- Hot-loop static assignment ----
    const int ctasPerTile = ncta / NTILE;          // ncta divisible by 8
    const int tile = bid / ctasPerTile;
    const int j    = bid - tile * ctasPerTile;
    const int tileNode0 = tile * TILE_N;
    const int tbeg = g_segptr[tile * N_NODES];
    const int tend = g_segptr[(tile + 1) * N_NODES];
    const int nch  = (tend - tbeg + 31) >> 5;      // 32-edge chunks in this tile

    const int wid  = tid >> 5;
    const int lane = tid & 31;
    const int gw   = j * (NTHREADS / 32) + wid;    // warp index within tile's CTA group
    const int tw   = ctasPerTile * (NTHREADS / 32);
    const int c0   = (int)((long long)nch * gw / tw);
    const int c1   = (int)((long long)nch * (gw + 1) / tw);

    const int  nodeE   = bid * chunkN + tid;
    const bool hasNode = (tid < chunkN) && (nodeE < N_NODES);

    for (int t = 0; t < T_STEPS; t++) {
        // ---- Phase 1: stage tile rates, then edge-parallel segmented-scan gather ----
        for (int i = tid; i < TILE_N; i += NTHREADS)
            s_r[i] = __ldcg(&g_Rh[tileNode0 + i]);
        __syncthreads();

        for (int ch = c0; ch < c1; ++ch) {         // uniform per-warp trip count
            const int e = tbeg + (ch << 5) + lane;
            const bool valid = (e < tend);
            int      seg = valid ? __ldg(&g_eseg[e]) : -1;   // coalesced
            unsigned m   = valid ? __ldg(&g_meta[e]) : 0u;   // coalesced; m=0 -> w=+0
            uint2 rh = s_r[m >> 16];                         // random LDS.64
            float w = __half2float(__ushort_as_half((unsigned short)(m & 0xFFFFu)));
            float2 f01 = __half22float2(*reinterpret_cast<__half2*>(&rh.x));
            float2 f23 = __half22float2(*reinterpret_cast<__half2*>(&rh.y));
            unsigned long long c01, c23;
            {
                float v0 = w * f01.x, v1 = w * f01.y, v2 = w * f23.x, v3 = w * f23.y;
                asm("mov.b64 %0, {%1, %2};" : "=l"(c01) : "f"(v0), "f"(v1));
                asm("mov.b64 %0, {%1, %2};" : "=l"(c23) : "f"(v2), "f"(v3));
            }
            // key-matched segmented inclusive scan (all lanes converged, full mask)
#pragma unroll
            for (int off = 1; off < 32; off <<= 1) {
                unsigned long long o01 = __shfl_up_sync(FULLMASK, c01, off);
                unsigned long long o23 = __shfl_up_sync(FULLMASK, c23, off);
                int os = __shfl_up_sync(FULLMASK, seg, off);
                unsigned long long s01, s23;
                asm("add.rn.f32x2 %0, %1, %2;" : "=l"(s01) : "l"(c01), "l"(o01));
                asm("add.rn.f32x2 %0, %1, %2;" : "=l"(s23) : "l"(c23), "l"(o23));
                bool p = (lane >= off) && (os == seg);
                c01 = p ? s01 : c01;
                c23 = p ? s23 : c23;
            }
            int ns = __shfl_down_sync(FULLMASK, seg, 1);
            bool tail = valid && (lane == 31 || ns != seg);
            if (tail) {
                float f0, f1, f2, f3;
                asm("mov.b64 {%0, %1}, %2;" : "=f"(f0), "=f"(f1) : "l"(c01));
                asm("mov.b64 {%0, %1}, %2;" : "=f"(f2), "=f"(f3) : "l"(c23));
                asm volatile("red.global.add.v4.f32 [%0], {%1, %2, %3, %4};"
                             :: "l"(&g_part[seg]), "f"(f0), "f"(f1), "f"(f2), "f"(f3)
                             : "memory");
            }
        }
        grid_bar(++barK);

        // ---- Phase 2: node-parallel Euler (all coalesced); consume + rezero parts ----
        if (hasNode) {
            float4 acc = make_float4(0.f, 0.f, 0.f, 0.f);
#pragma unroll
            for (int tl = 0; tl < NTILE; tl++) {
                float4* pp = &g_part[tl * N_NODES + nodeE];
                float4 p = __ldcg(pp);
                acc.x += p.x; acc.y += p.y; acc.z += p.z; acc.w += p.w;
                *pp = make_float4(0.f, 0.f, 0.f, 0.f);       // ready for next step
            }
            const float* xb = x + t * N_NODES + nodeE;
            float x0 = __ldcg(xb + 0 * TN);
            float x1 = __ldcg(xb + 1 * TN);
            float x2 = __ldcg(xb + 2 * TN);
            float x3 = __ldcg(xb + 3 * TN);

            float2 ab = g_ab[nodeE];
            float4 v  = g_V[nodeE];
            v.x = fmaf(ab.x, (ab.y - v.x) + (acc.x + x0), v.x);
            v.y = fmaf(ab.x, (ab.y - v.y) + (acc.y + x1), v.y);
            v.z = fmaf(ab.x, (ab.y - v.z) + (acc.z + x2), v.z);
            v.w = fmaf(ab.x, (ab.y - v.w) + (acc.w + x3), v.w);
            g_V[nodeE] = v;

            float r0 = fmaxf(v.x, 0.f), r1 = fmaxf(v.y, 0.f);
            float r2 = fmaxf(v.z, 0.f), r3 = fmaxf(v.w, 0.f);
            __half2 h01 = __floats2half2_rn(r0, r1);
            __half2 h23 = __floats2half2_rn(r2, r3);
            uint2 hp;
            hp.x = *reinterpret_cast<unsigned*>(&h01);
            hp.y = *reinterpret_cast<unsigned*>(&h23);
            g_Rh[nodeE] = hp;

            float* ob = out + t * N_NODES + nodeE;           // coalesced planes
            ob[0 * TN] = r0;
            ob[1 * TN] = r1;
            ob[2 * TN] = r2;
            ob[3 * TN] = r3;
        }
        if (t != T_STEPS - 1) grid_bar(++barK);
    }
}

extern "C" void kernel_launch(void* const* d_in, const int* in_sizes, int n_in,
                              void* d_out, int out_size) {
    const float* x      = (const float*)d_in[0];
    const float* bias   = (const float*)d_in[1];
    const float* tconst = (const float*)d_in[2];
    const float* sign   = (const float*)d_in[3];
    const float* cnt    = (const float*)d_in[4];
    const float* strg   = (const float*)d_in[5];
    const int*   src    = (const int*)d_in[6];
    const int*   tgt    = (const int*)d_in[7];
    float*       out    = (float*)d_out;

    // Attribute queries only (no alloc, no sync) -- capture-safe, deterministic.
    int nsm = 148;
    cudaDeviceGetAttribute(&nsm, cudaDevAttrMultiProcessorCount, 0);
    int ncta = (nsm * 3 / NTILE) * NTILE;    // multiple of NTILE, <= 3 per SM
    if (ncta > MAXCTA) ncta = MAXCTA;
    int chunkN = (N_NODES + ncta - 1) / ncta;
    int chunkS = (NSEG + ncta - 1) / ncta;   // <= 1024 for ncta >= 391

    static const int DYN = TILE_N * (int)sizeof(uint2);   // 50000 B
    cudaFuncSetAttribute(net_kernel, cudaFuncAttributeMaxDynamicSharedMemorySize, DYN);

    init_kernel<<<128, 512>>>();
    net_kernel<<<ncta, NTHREADS, DYN>>>(x, bias, tconst, sign, cnt, strg,
                                        src, tgt, out, chunkN, chunkS);
}

// round 16
// speedup vs baseline: 1.7124x; 1.6750x over previous
#include <cuda_runtime.h>
#include <cuda_fp16.h>

#define N_NODES  50000
#define N_EDGES  1600000
#define T_STEPS  50
#define DT_CONST 0.02f

#define NTHREADS 512
#define TN       (T_STEPS * N_NODES)
#define NTILE    8
#define TILE_N   6250                 // N_NODES / NTILE
#define NSEG     (NTILE * N_NODES)    // 400000 segments (tile, tgt)
#define NDBKT    32                   // degree buckets per tile
#define NBKT     (NTILE * NDBKT)      // 256 total buckets
#define MAXCTA   512

// ---------------- device scratch (static, no allocation) ----------------
__device__ int      g_segdeg[NSEG];
__device__ int      g_bktCnt[NBKT];
__device__ int      g_bktCur[NBKT];
__device__ int      g_rankOf[NSEG];      // seg -> rank (tile-major, degree-sorted)
__device__ int      g_sortedSeg[NSEG];   // rank -> seg
__device__ int      g_segptr[NSEG + 1];  // edge offsets over RANKS
__device__ int      g_cursor[NSEG];
__device__ unsigned g_meta[N_EDGES];     // (srcLocal<<16) | fp16(w), rank-sorted
__device__ float2   g_ab[N_NODES];       // {alpha, bias}
__device__ float4   g_V[N_NODES];        // membrane potential [n] x batch
__device__ uint2    g_Rh[N_NODES];       // fp16x4 rates (phases barrier-separated)
__device__ float4   g_part[NSEG];        // per-seg partials; consumed+rezeroed each step
__device__ int      g_blockSum[MAXCTA];
__device__ unsigned g_bar;

// ---------------- grid barrier (monotone counter, reset by init kernel) ----------------
__device__ __forceinline__ void grid_bar(unsigned k) {
    __syncthreads();
    if (threadIdx.x == 0) {
        __threadfence();
        atomicAdd(&g_bar, 1u);
        const unsigned target = k * gridDim.x;
        while (*(volatile unsigned*)&g_bar < target) { }
    }
    __syncthreads();
}

// ---------------- block-wide inclusive scan (Kogge-Stone in smem) ----------------
__device__ int block_scan_incl(int v) {
    __shared__ int ss[NTHREADS];
    const int tid = threadIdx.x;
    ss[tid] = v;
    __syncthreads();
#pragma unroll
    for (int off = 1; off < NTHREADS; off <<= 1) {
        int t = 0;
        if (tid >= off) t = ss[tid - off];
        __syncthreads();
        if (tid >= off) ss[tid] += t;
        __syncthreads();
    }
    return ss[tid];
}

// exclusive scan + block total (safe to call repeatedly)
__device__ int scan_excl_tot(int v, int& tot) {
    __shared__ int s_tot;
    int incl = block_scan_incl(v);
    if (threadIdx.x == NTHREADS - 1) s_tot = incl;
    __syncthreads();
    tot = s_tot;
    __syncthreads();
    return incl - v;
}

// ---------------- init kernel: reset per-launch mutable state ----------------
__global__ void init_kernel() {
    int i = blockIdx.x * blockDim.x + threadIdx.x;
    if (i == 0) g_bar = 0u;
    if (i < NBKT) g_bktCnt[i] = 0;
    for (int s = i; s < NSEG; s += gridDim.x * blockDim.x) g_segdeg[s] = 0;
}

// ---------------- main persistent kernel ----------------
__global__ void __launch_bounds__(NTHREADS, 3) net_kernel(
    const float* __restrict__ x,       // [B, T, N]
    const float* __restrict__ bias,    // [N]
    const float* __restrict__ tconst,  // [N]
    const float* __restrict__ sign,    // [E]
    const float* __restrict__ cnt,     // [E]
    const float* __restrict__ strg,    // [E]
    const int*   __restrict__ src,     // [E]
    const int*   __restrict__ tgt,     // [E]
    float*       __restrict__ out,     // [B, T, N]
    int chunkN, int chunkS)
{
    extern __shared__ uint2 s_r[];     // this step's rates for my tile (50KB)

    const int tid  = threadIdx.x;
    const int bid  = blockIdx.x;
    const int ncta = gridDim.x;
    const int gtid = bid * NTHREADS + tid;
    const int nthr = ncta * NTHREADS;
    unsigned barK = 0;

    // ---- Pass A: histogram over segments (tile(src), tgt) ----
    for (int e = gtid; e < N_EDGES; e += nthr) {
        int seg = (src[e] / TILE_N) * N_NODES + tgt[e];
        atomicAdd(&g_segdeg[seg], 1);
    }
    grid_bar(++barK);

    // ---- Pass A2: bucket histogram (tile-major, degree-sorted key) ----
    for (int s = gtid; s < NSEG; s += nthr) {
        int b = (s / N_NODES) * NDBKT + min(g_segdeg[s], NDBKT - 1);
        atomicAdd(&g_bktCnt[b], 1);
    }
    grid_bar(++barK);

    // ---- Pass A3: CTA0 exclusive-scans the 256 buckets -> cursors ----
    if (bid == 0) {
        int v = (tid < NBKT) ? g_bktCnt[tid] : 0;
        int t_;
        int ex = scan_excl_tot(v, t_);
        if (tid < NBKT) g_bktCur[tid] = ex;
    }
    grid_bar(++barK);

    // ---- Pass A4: assign ranks (within-bucket order arbitrary; same degree) ----
    for (int s = gtid; s < NSEG; s += nthr) {
        int b = (s / N_NODES) * NDBKT + min(g_segdeg[s], NDBKT - 1);
        int r = atomicAdd(&g_bktCur[b], 1);
        g_rankOf[s] = r;
        g_sortedSeg[r] = s;
    }
    grid_bar(++barK);

    // ---- Pass B1: per-CTA chunk scan of permuted degrees (2 rounds of 512) ----
    const int i0 = bid * chunkS + tid;
    const int i1 = i0 + NTHREADS;
    {
        int d0 = (tid < chunkS && i0 < NSEG) ? g_segdeg[g_sortedSeg[i0]] : 0;
        int d1 = (NTHREADS + tid < chunkS && i1 < NSEG) ? g_segdeg[g_sortedSeg[i1]] : 0;
        int tot0, tot1;
        int e0 = scan_excl_tot(d0, tot0);
        int e1 = scan_excl_tot(d1, tot1);
        if (tid < chunkS && i0 < NSEG) g_segptr[i0] = e0;
        if (NTHREADS + tid < chunkS && i1 < NSEG) g_segptr[i1] = e1 + tot0;
        if (tid == 0) g_blockSum[bid] = tot0 + tot1;
    }
    grid_bar(++barK);

    // ---- Pass B2: CTA0 exclusive-scans the block sums ----
    if (bid == 0) {
        int v = (tid < ncta) ? g_blockSum[tid] : 0;
        int t_;
        int ex = scan_excl_tot(v, t_);
        if (tid < ncta) g_blockSum[tid] = ex;
    }
    grid_bar(++barK);

    // ---- Pass B3: add block base -> final segptr & cursor (over ranks) ----
    {
        int boff = g_blockSum[bid];
        if (tid < chunkS && i0 < NSEG) {
            int v = g_segptr[i0] + boff;
            g_segptr[i0] = v;
            g_cursor[i0] = v;
        }
        if (NTHREADS + tid < chunkS && i1 < NSEG) {
            int v = g_segptr[i1] + boff;
            g_segptr[i1] = v;
            g_cursor[i1] = v;
        }
        if (gtid == 0) g_segptr[NSEG] = N_EDGES;
    }
    grid_bar(++barK);

    // ---- Pass C: scatter packed edge meta into rank-sorted slots ----
    for (int e = gtid; e < N_EDGES; e += nthr) {
        float w = sign[e] * fmaxf(cnt[e], 0.0f) * fmaxf(strg[e], 0.0f);
        int  s  = src[e];
        int  tile = s / TILE_N;
        int  sl   = s - tile * TILE_N;            // < 6250, fits 13 bits
        int  seg  = tile * N_NODES + tgt[e];
        int  rk   = g_rankOf[seg];
        int  p = atomicAdd(&g_cursor[rk], 1);
        unsigned hw = (unsigned)__half_as_ushort(__float2half_rn(w));
        g_meta[p] = ((unsigned)sl << 16) | hw;
    }

    // ---- Pass D: node state init + zero partials ----
    for (int n = gtid; n < N_NODES; n += nthr) {
        float b   = bias[n];
        float tau = fmaxf(tconst[n], DT_CONST);
        g_ab[n] = make_float2(DT_CONST / tau, b);
        g_V[n]  = make_float4(b, b, b, b);
        float r = fmaxf(b, 0.0f);
        __half2 h = __floats2half2_rn(r, r);
        uint2 hp;
        hp.x = *reinterpret_cast<unsigned*>(&h);
        hp.y = hp.x;
        g_Rh[n] = hp;
    }
    for (int s = gtid; s < NSEG; s += nthr)
        g_part[s] = make_float4(0.f, 0.f, 0.f, 0.f);
    grid_bar(++barK);   // meta + segptr + ranks + state all visible

    // ---- Hot-loop static assignment ----
    const int ctasPerTile = ncta / NTILE;          // ncta divisible by 8
    const int tile = bid / ctasPerTile;
    const int j    = bid - tile * ctasPerTile;
    const int tileNode0 = tile * TILE_N;
    const int rbase = tile * N_NODES;              // tile's rank range = [rbase, rbase+N)
    const int G     = ctasPerTile * NTHREADS;      // threads per tile group (29184)
    const int gthr  = j * NTHREADS + tid;
    // round 0 rank: rbase+gthr (deg ascending). round 1: mirrored high end.
    const int loc1  = N_NODES - 1 - gthr;
    const bool has1 = (loc1 >= G);                 // covers [G, N) exactly; needs 2G >= N

    const int  nodeE   = bid * chunkN + tid;
    const bool hasNode = (tid < chunkN) && (nodeE < N_NODES);

    for (int t = 0; t < T_STEPS; t++) {
        // ---- Phase 1: stage tile rates, then degree-uniform segment gather ----
        for (int i = tid; i < TILE_N; i += NTHREADS)
            s_r[i] = __ldcg(&g_Rh[tileNode0 + i]);
        __syncthreads();

#pragma unroll
        for (int round = 0; round < 2; round++) {
            int r;
            if (round == 0) r = rbase + gthr;
            else { if (!has1) break; r = rbase + loc1; }
            const int e0 = __ldg(&g_segptr[r]);
            const int e1 = __ldg(&g_segptr[r + 1]);
            if (e1 > e0) {
                float a0 = 0.f, a1 = 0.f, a2 = 0.f, a3 = 0.f;
                for (int e = e0; e < e1; ++e) {
                    unsigned m = __ldg(&g_meta[e]);          // coalesced-ish 4B
                    uint2 rh = s_r[m >> 16];                 // random LDS.64 (cheap)
                    float w = __half2float(__ushort_as_half((unsigned short)(m & 0xFFFFu)));
                    float2 f01 = __half22float2(*reinterpret_cast<__half2*>(&rh.x));
                    float2 f23 = __half22float2(*reinterpret_cast<__half2*>(&rh.y));
                    a0 = fmaf(w, f01.x, a0);
                    a1 = fmaf(w, f01.y, a1);
                    a2 = fmaf(w, f23.x, a2);
                    a3 = fmaf(w, f23.y, a3);
                }
                int seg = __ldg(&g_sortedSeg[r]);            // coalesced
                g_part[seg] = make_float4(a0, a1, a2, a3);   // scattered STG.128, f&f
            }
        }
        grid_bar(++barK);

        // ---- Phase 2: node-parallel Euler (all coalesced); consume + rezero parts ----
        if (hasNode) {
            float4 acc = make_float4(0.f, 0.f, 0.f, 0.f);
#pragma unroll
            for (int tl = 0; tl < NTILE; tl++) {
                float4* pp = &g_part[tl * N_NODES + nodeE];
                float4 p = __ldcg(pp);
                acc.x += p.x; acc.y += p.y; acc.z += p.z; acc.w += p.w;
                *pp = make_float4(0.f, 0.f, 0.f, 0.f);       // ready for next step
            }
            const float* xb = x + t * N_NODES + nodeE;
            float x0 = __ldcg(xb + 0 * TN);
            float x1 = __ldcg(xb + 1 * TN);
            float x2 = __ldcg(xb + 2 * TN);
            float x3 = __ldcg(xb + 3 * TN);

            float2 ab = g_ab[nodeE];
            float4 v  = g_V[nodeE];
            v.x = fmaf(ab.x, (ab.y - v.x) + (acc.x + x0), v.x);
            v.y = fmaf(ab.x, (ab.y - v.y) + (acc.y + x1), v.y);
            v.z = fmaf(ab.x, (ab.y - v.z) + (acc.z + x2), v.z);
            v.w = fmaf(ab.x, (ab.y - v.w) + (acc.w + x3), v.w);
            g_V[nodeE] = v;

            float r0 = fmaxf(v.x, 0.f), r1 = fmaxf(v.y, 0.f);
            float r2 = fmaxf(v.z, 0.f), r3 = fmaxf(v.w, 0.f);
            __half2 h01 = __floats2half2_rn(r0, r1);
            __half2 h23 = __floats2half2_rn(r2, r3);
            uint2 hp;
            hp.x = *reinterpret_cast<unsigned*>(&h01);
            hp.y = *reinterpret_cast<unsigned*>(&h23);
            g_Rh[nodeE] = hp;

            float* ob = out + t * N_NODES + nodeE;           // coalesced planes
            ob[0 * TN] = r0;
            ob[1 * TN] = r1;
            ob[2 * TN] = r2;
            ob[3 * TN] = r3;
        }
        if (t != T_STEPS - 1) grid_bar(++barK);
    }
}

extern "C" void kernel_launch(void* const* d_in, const int* in_sizes, int n_in,
                              void* d_out, int out_size) {
    const float* x      = (const float*)d_in[0];
    const float* bias   = (const float*)d_in[1];
    const float* tconst = (const float*)d_in[2];
    const float* sign   = (const float*)d_in[3];
    const float* cnt    = (const float*)d_in[4];
    const float* strg   = (const float*)d_in[5];
    const int*   src    = (const int*)d_in[6];
    const int*   tgt    = (const int*)d_in[7];
    float*       out    = (float*)d_out;

    // Attribute queries only (no alloc, no sync) -- capture-safe, deterministic.
    int nsm = 148;
    cudaDeviceGetAttribute(&nsm, cudaDevAttrMultiProcessorCount, 0);
    int ncta = (nsm * 3 / NTILE) * NTILE;    // multiple of NTILE, <= 3 per SM
    if (ncta > MAXCTA) ncta = MAXCTA;
    int chunkN = (N_NODES + ncta - 1) / ncta;
    int chunkS = (NSEG + ncta - 1) / ncta;   // <= 1024 for ncta >= 391

    static const int DYN = TILE_N * (int)sizeof(uint2);   // 50000 B
    cudaFuncSetAttribute(net_kernel, cudaFuncAttributeMaxDynamicSharedMemorySize, DYN);

    init_kernel<<<128, 512>>>();
    net_kernel<<<ncta, NTHREADS, DYN>>>(x, bias, tconst, sign, cnt, strg,
                                        src, tgt, out, chunkN, chunkS);
}

// round 17
// speedup vs baseline: 2.7550x; 1.6088x over previous
#include <cuda_runtime.h>
#include <cuda_fp16.h>

#define N_NODES  50000
#define N_EDGES  1600000
#define T_STEPS  50
#define DT_CONST 0.02f

#define NTHREADS 512
#define TN       (T_STEPS * N_NODES)
#define QPC      (NTHREADS / 4)     // 128 quads per CTA
#define MAXCTA   512                // scan width bound
#define MAXQ     (MAXCTA * QPC)
#define ECAP     8192               // smem edge capacity per CTA (32KB packed)

// ---------------- device scratch (static, no allocation) ----------------
__device__ int      g_deg[N_NODES];
__device__ int      g_rowptr[N_NODES + 1];
__device__ int      g_cursor[N_NODES];
__device__ int      g_rowLo[MAXQ + 1];      // quad -> first row of its contiguous range
__device__ unsigned g_wp[N_EDGES];          // packed edge: (src<<16) | fp16(w)
__device__ float2   g_ab[N_NODES];          // {alpha, bias}
__device__ float    g_Vf[N_NODES * 4];      // membrane potential [n][b]
__device__ float4   g_R[2][N_NODES];        // double-buffered relu(v) fp32
__device__ int      g_blockSum[MAXCTA];
__device__ unsigned g_bar;

// ---------------- grid barrier (monotone counter, reset by init kernel) ----------------
__device__ __forceinline__ void grid_bar(unsigned k) {
    __syncthreads();
    if (threadIdx.x == 0) {
        __threadfence();
        atomicAdd(&g_bar, 1u);
        const unsigned target = k * gridDim.x;
        while (*(volatile unsigned*)&g_bar < target) { }
    }
    __syncthreads();
}

// ---------------- block-wide inclusive scan (Kogge-Stone in smem) ----------------
__device__ int block_scan_incl(int v) {
    __shared__ int ss[NTHREADS];
    const int tid = threadIdx.x;
    ss[tid] = v;
    __syncthreads();
#pragma unroll
    for (int off = 1; off < NTHREADS; off <<= 1) {
        int t = 0;
        if (tid >= off) t = ss[tid - off];
        __syncthreads();
        if (tid >= off) ss[tid] += t;
        __syncthreads();
    }
    return ss[tid];
}

__device__ __forceinline__ int quad_of_offset(int off, int nquads) {
    return (int)(((long long)off * nquads) / N_EDGES);
}

// ---------------- init kernel: reset per-launch mutable state ----------------
__global__ void init_kernel() {
    int i = blockIdx.x * blockDim.x + threadIdx.x;
    if (i == 0) g_bar = 0u;
    for (int n = i; n < N_NODES; n += gridDim.x * blockDim.x) g_deg[n] = 0;
}

// ---------------- fallback hot loop (global edges; proven R5 shape) ----------------
__device__ __noinline__ void run_steps_fallback(
    int rowA, int rowB, int q, unsigned qmask,
    const float* __restrict__ x, float* __restrict__ out,
    unsigned& barK)
{
    for (int t = 0; t < T_STEPS; t++) {
        const float4* __restrict__ Rc  = g_R[t & 1];
        float*        __restrict__ Rnf = (float*)(g_R[(t + 1) & 1]);
        const float*  __restrict__ xt  = x + t * N_NODES;
        float*        __restrict__ ot  = out + t * N_NODES;

        for (int r = rowA; r < rowB; ++r) {
            const int beg = g_rowptr[r];
            const int end = g_rowptr[r + 1];
            const float xv = __ldcg(xt + q * TN + r);
            float a0 = 0.f, a1 = 0.f, a2 = 0.f, a3 = 0.f;
            for (int e = beg + q; e < end; e += 4) {
                unsigned u = __ldg(&g_wp[e]);
                float w = __half2float(__ushort_as_half((unsigned short)(u & 0xFFFFu)));
                float4 rv = __ldcg(&Rc[u >> 16]);
                a0 = fmaf(w, rv.x, a0); a1 = fmaf(w, rv.y, a1);
                a2 = fmaf(w, rv.z, a2); a3 = fmaf(w, rv.w, a3);
            }
#pragma unroll
            for (int off = 1; off < 4; off <<= 1) {
                a0 += __shfl_xor_sync(qmask, a0, off);
                a1 += __shfl_xor_sync(qmask, a1, off);
                a2 += __shfl_xor_sync(qmask, a2, off);
                a3 += __shfl_xor_sync(qmask, a3, off);
            }
            float acc = (q == 0) ? a0 : (q == 1) ? a1 : (q == 2) ? a2 : a3;
            float2 ab = g_ab[r];
            float  v  = g_Vf[4 * r + q];
            v = fmaf(ab.x, (ab.y - v) + (acc + xv), v);
            g_Vf[4 * r + q] = v;
            float rr = fmaxf(v, 0.0f);
            Rnf[4 * r + q] = rr;
            ot[q * TN + r] = rr;
        }
        if (t != T_STEPS - 1) grid_bar(++barK);
    }
}

// ---------------- main persistent kernel ----------------
__global__ void __launch_bounds__(NTHREADS, 2) net_kernel(
    const float* __restrict__ x,       // [B, T, N]
    const float* __restrict__ bias,    // [N]
    const float* __restrict__ tconst,  // [N]
    const float* __restrict__ sign,    // [E]
    const float* __restrict__ cnt,     // [E]
    const float* __restrict__ strg,    // [E]
    const int*   __restrict__ src,     // [E]
    const int*   __restrict__ tgt,     // [E]
    float*       __restrict__ out,     // [B, T, N]
    int chunk)
{
    __shared__ unsigned s_ws[ECAP];    // packed edge slice (32KB)

    const int tid   = threadIdx.x;
    const int bid   = blockIdx.x;
    const int ncta  = gridDim.x;
    const int gtid  = bid * NTHREADS + tid;
    const int nthr  = ncta * NTHREADS;
    const int nquads = ncta * QPC;
    unsigned barK = 0;

    // ---- Pass A: degree histogram over targets ----
    for (int e = gtid; e < N_EDGES; e += nthr)
        atomicAdd(&g_deg[tgt[e]], 1);
    grid_bar(++barK);

    // ---- Pass B1: per-CTA chunk sums ----
    {
        const int n = bid * chunk + tid;
        int v = (tid < chunk && n < N_NODES) ? g_deg[n] : 0;
        int incl = block_scan_incl(v);
        if (tid == NTHREADS - 1) g_blockSum[bid] = incl;
    }
    grid_bar(++barK);

    // ---- Pass B2: CTA0 exclusive-scans the block sums ----
    if (bid == 0) {
        int v = (tid < ncta) ? g_blockSum[tid] : 0;
        int incl = block_scan_incl(v);
        if (tid < ncta) g_blockSum[tid] = incl - v;
    }
    grid_bar(++barK);

    // ---- Pass B3: per-chunk exclusive scan -> row_ptr & cursor ----
    {
        const int n = bid * chunk + tid;
        int v = (tid < chunk && n < N_NODES) ? g_deg[n] : 0;
        int incl = block_scan_incl(v);
        if (tid < chunk && n < N_NODES) {
            int rp = g_blockSum[bid] + incl - v;
            g_rowptr[n] = rp;
            g_cursor[n] = rp;
        }
        if (gtid == 0) g_rowptr[N_NODES] = N_EDGES;
    }
    grid_bar(++barK);

    // ---- Pass C: scatter packed edges into CSR slots ----
    for (int e = gtid; e < N_EDGES; e += nthr) {
        float w = sign[e] * fmaxf(cnt[e], 0.0f) * fmaxf(strg[e], 0.0f);
        int  t = tgt[e];
        int  p = atomicAdd(&g_cursor[t], 1);
        unsigned hw = (unsigned)__half_as_ushort(__float2half_rn(w));
        g_wp[p] = ((unsigned)src[e] << 16) | hw;
    }

    // ---- Edge-balanced quad->row-range partition ----
    for (int r = gtid; r <= N_NODES; r += nthr) {
        int a, b;
        if (r == N_NODES) {
            a = min(quad_of_offset(g_rowptr[N_NODES - 1], nquads), nquads - 1) + 1;
            b = nquads;
        } else {
            b = min(quad_of_offset(g_rowptr[r], nquads), nquads - 1);
            a = (r == 0) ? 0 : min(quad_of_offset(g_rowptr[r - 1], nquads), nquads - 1) + 1;
        }
        for (int qq = a; qq <= b; qq++) g_rowLo[qq] = r;
    }

    // ---- Pass D: node state init ----
    for (int n = gtid; n < N_NODES; n += nthr) {
        float b   = bias[n];
        float tau = fmaxf(tconst[n], DT_CONST);
        g_ab[n] = make_float2(DT_CONST / tau, b);
        float r = fmaxf(b, 0.0f);
        g_Vf[4 * n + 0] = b; g_Vf[4 * n + 1] = b;
        g_Vf[4 * n + 2] = b; g_Vf[4 * n + 3] = b;
        g_R[0][n] = make_float4(r, r, r, r);
    }
    grid_bar(++barK);   // edges + partition + state all visible now

    // ---- Stage this CTA's packed edge slice into shared memory ----
    const int rowA_cta = g_rowLo[bid * QPC];
    const int rowB_cta = g_rowLo[(bid + 1) * QPC];
    const int ebase    = g_rowptr[rowA_cta];
    const int ecnt     = g_rowptr[rowB_cta] - ebase;
    const bool fits    = (ecnt <= ECAP);
    if (fits) {
        for (int i = tid; i < ecnt; i += NTHREADS)
            s_ws[i] = g_wp[ebase + i];
    }
    __syncthreads();

    const int q    = tid & 3;
    const int qid  = gtid >> 2;
    const int rowA = g_rowLo[qid];
    const int rowB = g_rowLo[qid + 1];
    const unsigned qmask = 0xFu << (tid & 28);

    if (!fits) {
        run_steps_fallback(rowA, rowB, q, qmask, x, out, barK);
        return;
    }

    // ---- Hot loop: 50 steps, quad-per-row-range gather SpMV + Euler update ----
    for (int t = 0; t < T_STEPS; t++) {
        const float4* __restrict__ Rc  = g_R[t & 1];
        float*        __restrict__ Rnf = (float*)(g_R[(t + 1) & 1]);
        const float*  __restrict__ xt  = x + t * N_NODES;
        float*        __restrict__ ot  = out + t * N_NODES;

        for (int r = rowA; r < rowB; ++r) {
            const int beg = g_rowptr[r];          // L1-hit (same addr each step)
            const int end = g_rowptr[r + 1];
            const float xv = __ldcg(xt + q * TN + r);

            unsigned long long a01 = 0ull, a23 = 0ull;   // f32x2 accumulators
#pragma unroll 8
            for (int e = beg + q; e < end; e += 4) {
                unsigned u = s_ws[e - ebase];     // LDS.32 (1 wavefront)
                float w = __half2float(__ushort_as_half((unsigned short)(u & 0xFFFFu)));
                unsigned long long w2, r01, r23;
                asm("mov.b64 %0, {%1, %1};" : "=l"(w2) : "f"(w));
                asm volatile("ld.global.cg.v2.b64 {%0, %1}, [%2];"
                             : "=l"(r01), "=l"(r23) : "l"(Rc + (u >> 16)));
                asm("fma.rn.f32x2 %0, %1, %2, %3;" : "=l"(a01) : "l"(w2), "l"(r01), "l"(a01));
                asm("fma.rn.f32x2 %0, %1, %2, %3;" : "=l"(a23) : "l"(w2), "l"(r23), "l"(a23));
            }
            // quad reduction with quad-local mask (quads diverge; quad lanes don't)
#pragma unroll
            for (int off = 1; off < 4; off <<= 1) {
                unsigned long long b01 = __shfl_xor_sync(qmask, a01, off);
                unsigned long long b23 = __shfl_xor_sync(qmask, a23, off);
                asm("add.rn.f32x2 %0, %1, %2;" : "=l"(a01) : "l"(a01), "l"(b01));
                asm("add.rn.f32x2 %0, %1, %2;" : "=l"(a23) : "l"(a23), "l"(b23));
            }
            unsigned long long sel = (q < 2) ? a01 : a23;
            float lo, hi;
            asm("mov.b64 {%0, %1}, %2;" : "=f"(lo), "=f"(hi) : "l"(sel));
            float acc = (q & 1) ? hi : lo;

            float2 ab = g_ab[r];                  // L1-hit
            float  v  = g_Vf[4 * r + q];          // L1-hit
            v = fmaf(ab.x, (ab.y - v) + (acc + xv), v);
            g_Vf[4 * r + q] = v;
            float rr = fmaxf(v, 0.0f);
            Rnf[4 * r + q] = rr;
            ot[q * TN + r] = rr;
        }
        if (t != T_STEPS - 1) grid_bar(++barK);
    }
}

extern "C" void kernel_launch(void* const* d_in, const int* in_sizes, int n_in,
                              void* d_out, int out_size) {
    const float* x      = (const float*)d_in[0];
    const float* bias   = (const float*)d_in[1];
    const float* tconst = (const float*)d_in[2];
    const float* sign   = (const float*)d_in[3];
    const float* cnt    = (const float*)d_in[4];
    const float* strg   = (const float*)d_in[5];
    const int*   src    = (const int*)d_in[6];
    const int*   tgt    = (const int*)d_in[7];
    float*       out    = (float*)d_out;

    // Attribute query only (no alloc, no sync) -- capture-safe, deterministic.
    int nsm = 148;
    cudaDeviceGetAttribute(&nsm, cudaDevAttrMultiProcessorCount, 0);
    int ncta = nsm * 2;                // 2 CTAs/SM -> 64 regs/thread for deep MLP
    if (ncta > MAXCTA) ncta = MAXCTA;
    int chunk = (N_NODES + ncta - 1) / ncta;

    init_kernel<<<128, 512>>>();
    net_kernel<<<ncta, NTHREADS>>>(x, bias, tconst, sign, cnt, strg, src, tgt, out, chunk);
}